// round 16
// baseline (speedup 1.0000x reference)
#include <cuda_runtime.h>
#include <cuda_bf16.h>
#include <cstdint>

// FINAL (R13/R15-confirmed optimum).
// Batched scatter-add: out[b, tgt[b,e], :] += messages[b, e, :]
//   messages (B=32, E=8192, D=128) fp32 | tgt (B=32, E=8192) int32
//   out      (B=32, N=2048, D=128) fp32
//
// Structure (each element evidence-backed over 15 rounds):
//  - zero kernel + PDL: scatter grid launches while zeroing runs; its
//    pre-wait load prologue overlaps the zero stores (R9/R13 WINs).
//  - scatter: one warp per 8 edge rows; 4 rows loaded pre-wait (covers the
//    PDL window at ~60 regs), 4 rows loaded post-wait under the first
//    batch's RED issue (R13: best kernel time, 33.9us, reproducible).
//  - red.global.add.v4.f32: one vector no-return atomic per 16B — the
//    scatter is bounded by L2 RMW service (~34us), invariant across
//    engines/occupancy (R1-R7 sweep), so this is the floor.
static constexpr int B = 32;
static constexpr int E = 8192;
static constexpr int N = 2048;
static constexpr int D = 128;               // 32 float4 per row
static constexpr int ROWS = 8;              // rows per warp (4 pre-wait + 4 post)
static constexpr int WARPS = 8;             // warps per block
static constexpr int OUT_F4 = B * N * D / 4;   // 2097152 float4

// ── Primary: zero the output. PDL trigger at entry; 2x-unrolled STG.128.
__global__ __launch_bounds__(256) void zero_out(float4* __restrict__ out4)
{
    asm volatile("griddepcontrol.launch_dependents;" ::: "memory");
    const float4 z = make_float4(0.f, 0.f, 0.f, 0.f);
    const int stride = gridDim.x * 512;
    int i = blockIdx.x * 512 + threadIdx.x;
    for (; i + 256 < OUT_F4; i += stride) {
        out4[i]       = z;
        out4[i + 256] = z;
    }
    if (i < OUT_F4) out4[i] = z;
}

// ── Secondary (PDL): rows 0..3 load pre-wait; rows 4..7 load post-wait,
//    issued before scattering rows 0..3 so their latency hides under the
//    first batch's RED issue.
__global__ __launch_bounds__(WARPS * 32) void scatter_add(
    const float4* __restrict__ messages,   // (B*E, 32) float4
    const int*    __restrict__ tgt,        // (B*E,)
    float*        __restrict__ out)        // (B*N*D,)
{
    const int warp = blockIdx.x * WARPS + (threadIdx.x >> 5);
    const int lane = threadIdx.x & 31;
    const int row0 = warp * ROWS;

    // Index fetch: lanes 0..3 load int2 pairs (one 32B sector).
    int t = 0, t2 = 0;
    if (lane < ROWS / 2) {
        const int2 p = __ldg((const int2*)&tgt[row0 + lane * 2]);
        t  = p.x;
        t2 = p.y;
    }

    // Pre-wait batch: rows 0..3.
    float4 v[4];
#pragma unroll
    for (int r = 0; r < 4; r++)
        v[r] = __ldcs(&messages[(size_t)(row0 + r) * 32 + lane]);

    asm volatile("griddepcontrol.wait;" ::: "memory");

    // Post-wait batch: rows 4..7 first, then scatter both batches.
    float4 w[4];
#pragma unroll
    for (int r = 0; r < 4; r++)
        w[r] = __ldcs(&messages[(size_t)(row0 + 4 + r) * 32 + lane]);

#pragma unroll
    for (int r = 0; r < 4; r++) {
        const int src = r >> 1;
        const int tr  = (r & 1) ? __shfl_sync(0xFFFFFFFFu, t2, src)
                                : __shfl_sync(0xFFFFFFFFu, t,  src);
        const int b   = (row0 + r) >> 13;
        float* dst = out + ((size_t)(b * N + tr) * D) + lane * 4;
        asm volatile(
            "red.global.add.v4.f32 [%0], {%1, %2, %3, %4};"
            :: "l"(dst), "f"(v[r].x), "f"(v[r].y), "f"(v[r].z), "f"(v[r].w)
            : "memory");
    }
#pragma unroll
    for (int r = 4; r < 8; r++) {
        const int src = r >> 1;
        const int tr  = (r & 1) ? __shfl_sync(0xFFFFFFFFu, t2, src)
                                : __shfl_sync(0xFFFFFFFFu, t,  src);
        const int b   = (row0 + r) >> 13;
        float* dst = out + ((size_t)(b * N + tr) * D) + lane * 4;
        asm volatile(
            "red.global.add.v4.f32 [%0], {%1, %2, %3, %4};"
            :: "l"(dst), "f"(w[r - 4].x), "f"(w[r - 4].y),
               "f"(w[r - 4].z), "f"(w[r - 4].w)
            : "memory");
    }
}

extern "C" void kernel_launch(void* const* d_in, const int* in_sizes, int n_in,
                              void* d_out, int out_size)
{
    const float4* messages = (const float4*)d_in[0];
    const int*    tgt      = (const int*)d_in[1];

    // Primary: zero kernel.
    zero_out<<<1184, 256>>>((float4*)d_out);

    // Secondary: scatter with programmatic dependent launch.
    cudaLaunchConfig_t cfg = {};
    const int total_rows = B * E;                       // 262144
    cfg.gridDim  = dim3(total_rows / (WARPS * ROWS));   // 4096
    cfg.blockDim = dim3(WARPS * 32);
    cfg.dynamicSmemBytes = 0;
    cfg.stream = 0;
    cudaLaunchAttribute attr[1];
    attr[0].id = cudaLaunchAttributeProgrammaticStreamSerialization;
    attr[0].val.programmaticStreamSerializationAllowed = 1;
    cfg.attrs = attr;
    cfg.numAttrs = 1;
    cudaLaunchKernelEx(&cfg, scatter_add, messages, tgt, (float*)d_out);
}